// round 1
// baseline (speedup 1.0000x reference)
#include <cuda_runtime.h>

// Problem constants
#define NMB 32          // N*M
#define TLEN 300
#define VJ 25
#define CH 64
#define KT 9
#define NSKEL (NMB*TLEN)          // 9600 skeletons
#define NROWS (NSKEL*VJ)          // 240000

// -------- scratch (static device allocations are allowed) --------
__device__ float g_xg[NMB*VJ*TLEN*CH];   // GCN output in (nm, v, t, c)
__device__ float g_Ahat[VJ*VJ];          // norm[v]*adj[v,u]*norm[u]
__device__ float g_wt[CH*KT*CH];         // conv weight transposed [ci][k][co]
__device__ float g_scale[CH];            // BN fold: gamma/sqrt(var+eps)
__device__ float g_shift[CH];            // (conv_b - mean)*scale + beta

// ============================ prep ============================
__global__ void prep_kernel(const float* __restrict__ adj,
                            const float* __restrict__ conv_w,
                            const float* __restrict__ conv_b,
                            const float* __restrict__ bn_gamma,
                            const float* __restrict__ bn_beta,
                            const float* __restrict__ bn_mean,
                            const float* __restrict__ bn_var) {
    __shared__ float norm[VJ];
    int tid = threadIdx.x;
    if (tid < VJ) {
        float s = 0.f;
        for (int u = 0; u < VJ; u++) s += adj[tid*VJ + u];
        norm[tid] = rsqrtf(s);
    }
    __syncthreads();
    if (tid < CH) {
        float inv = bn_gamma[tid] * rsqrtf(bn_var[tid] + 1e-5f);
        g_scale[tid] = inv;
        g_shift[tid] = (conv_b[tid] - bn_mean[tid]) * inv + bn_beta[tid];
    }
    for (int i = tid; i < VJ*VJ; i += blockDim.x)
        g_Ahat[i] = norm[i/VJ] * adj[i] * norm[i%VJ];
    // conv_w is (co, ci, k, 1) row-major -> g_wt[ci][k][co]
    for (int i = tid; i < CH*CH*KT; i += blockDim.x) {
        int ci = i / (KT*CH);
        int k  = (i / CH) % KT;
        int co = i % CH;
        g_wt[i] = conv_w[(co*CH + ci)*KT + k];
    }
}

// ============================ GCN ============================
// Block handles 4 skeletons = 100 rows (padded to 112).
// smem: hs[112][64], hw[112][64], Ws[64][64], gb[64], Ah[625]
#define GCN_S 4
#define GCN_ROWS (GCN_S*VJ)   // 100
#define GCN_RPAD 112

__global__ __launch_bounds__(256, 2)
void gcn_kernel(const float* __restrict__ h,
                const float* __restrict__ gcn_w,
                const float* __restrict__ gcn_b) {
    extern __shared__ float sm[];
    float* hs = sm;                         // 112*64
    float* hw = hs + GCN_RPAD*CH;           // 112*64
    float* Ws = hw + GCN_RPAD*CH;           // 64*64
    float* gb = Ws + CH*CH;                 // 64
    float* Ah = gb + CH;                    // 625

    const int tid = threadIdx.x;
    const int g0  = blockIdx.x * GCN_S;
    const float* hbase = h + (long long)g0 * VJ * CH;

    for (int i = tid; i < GCN_RPAD*CH; i += 256)
        hs[i] = (i < GCN_ROWS*CH) ? hbase[i] : 0.f;
    for (int i = tid; i < CH*CH; i += 256) Ws[i] = gcn_w[i];
    for (int i = tid; i < VJ*VJ; i += 256) Ah[i] = g_Ahat[i];
    if (tid < CH) gb[tid] = gcn_b[tid];
    __syncthreads();

    const int tx = tid & 15, ty = tid >> 4;
    const int c4 = tx * 4;

    // GEMM: hw = hs @ Ws, thread tile = 7 rows x 4 cols
    float4 acc[7];
#pragma unroll
    for (int j = 0; j < 7; j++) acc[j] = make_float4(0.f,0.f,0.f,0.f);

#pragma unroll 2
    for (int ci4 = 0; ci4 < 16; ci4++) {
        float4 w0 = *(const float4*)&Ws[(ci4*4+0)*CH + c4];
        float4 w1 = *(const float4*)&Ws[(ci4*4+1)*CH + c4];
        float4 w2 = *(const float4*)&Ws[(ci4*4+2)*CH + c4];
        float4 w3 = *(const float4*)&Ws[(ci4*4+3)*CH + c4];
#pragma unroll
        for (int j = 0; j < 7; j++) {
            float4 hv = *(const float4*)&hs[(ty + 16*j)*CH + ci4*4];
            acc[j].x += hv.x*w0.x + hv.y*w1.x + hv.z*w2.x + hv.w*w3.x;
            acc[j].y += hv.x*w0.y + hv.y*w1.y + hv.z*w2.y + hv.w*w3.y;
            acc[j].z += hv.x*w0.z + hv.y*w1.z + hv.z*w2.z + hv.w*w3.z;
            acc[j].w += hv.x*w0.w + hv.y*w1.w + hv.z*w2.w + hv.w*w3.w;
        }
    }
#pragma unroll
    for (int j = 0; j < 7; j++)
        *(float4*)&hw[(ty + 16*j)*CH + c4] = acc[j];
    __syncthreads();

    // Aggregation: out[s,v,c] = relu(sum_u Ah[v,u]*hw[s*25+u,c] + gb[c])
    const float4 gbv = *(const float4*)&gb[c4];
#pragma unroll
    for (int j = 0; j < 7; j++) {
        int r = ty + 16*j;
        if (r >= GCN_ROWS) break;
        int s = r / VJ, v = r % VJ;
        float4 a = gbv;
#pragma unroll
        for (int u = 0; u < VJ; u++) {
            float av = Ah[v*VJ + u];
            float4 xv = *(const float4*)&hw[(s*VJ + u)*CH + c4];
            a.x += av*xv.x; a.y += av*xv.y; a.z += av*xv.z; a.w += av*xv.w;
        }
        a.x = fmaxf(a.x, 0.f); a.y = fmaxf(a.y, 0.f);
        a.z = fmaxf(a.z, 0.f); a.w = fmaxf(a.w, 0.f);
        int g  = g0 + s;
        int nm = g / TLEN, t = g % TLEN;
        *(float4*)&g_xg[((nm*VJ + v)*TLEN + t)*CH + c4] = a;
    }
}

// ============================ Conv + BN + ReLU + residual ============================
// Block = one (nm, v) slab: x[300][64] padded to [308][64] in smem.
// Weights streamed in 8-cin chunks: ws[8][9][64].
// Thread: q = tid%16 -> 4 contiguous c_out; tg = tid/16 -> t = half*150 + tg + 16*i, i<10.
#define CIN_CHUNK 8
#define XS_ROWS (TLEN + KT - 1)  // 308

__global__ __launch_bounds__(256, 2)
void conv_kernel(const float* __restrict__ h, float* __restrict__ out) {
    extern __shared__ float sm[];
    float* xs = sm;                      // 308*64
    float* ws = xs + XS_ROWS*CH;         // 8*9*64

    const int tid = threadIdx.x;
    const int slab = blockIdx.x;         // nm*25 + v
    const int nm = slab / VJ, v = slab % VJ;
    const float* xg = g_xg + (long long)slab * TLEN * CH;

    for (int i = tid; i < XS_ROWS*CH; i += 256) {
        int row = i >> 6;  // /64
        xs[i] = (row >= 4 && row < 4 + TLEN) ? xg[i - 4*CH] : 0.f;
    }

    const int q = tid & 15, tg = tid >> 4;
    const int c4 = q * 4;
    float4 scl = make_float4(g_scale[c4], g_scale[c4+1], g_scale[c4+2], g_scale[c4+3]);
    float4 sft = make_float4(g_shift[c4], g_shift[c4+1], g_shift[c4+2], g_shift[c4+3]);

    for (int th = 0; th < 2; th++) {
        int tb[10];
#pragma unroll
        for (int i = 0; i < 10; i++) {
            int tl = tg + 16*i;
            tb[i] = (tl < 150) ? (th*150 + tl) : 0;
        }
        float4 acc[10];
#pragma unroll
        for (int i = 0; i < 10; i++) acc[i] = make_float4(0.f,0.f,0.f,0.f);

        for (int cc = 0; cc < CH/CIN_CHUNK; cc++) {
            __syncthreads();   // prior readers of ws done (also orders first xs fill)
            for (int i = tid; i < CIN_CHUNK*KT*CH; i += 256)
                ws[i] = g_wt[cc*CIN_CHUNK*KT*CH + i];
            __syncthreads();

#pragma unroll 1
            for (int k = 0; k < KT; k++) {
#pragma unroll
                for (int ci4 = 0; ci4 < 2; ci4++) {
                    int cib = cc*CIN_CHUNK + ci4*4;
                    float4 w0 = *(const float4*)&ws[((ci4*4+0)*KT + k)*CH + c4];
                    float4 w1 = *(const float4*)&ws[((ci4*4+1)*KT + k)*CH + c4];
                    float4 w2 = *(const float4*)&ws[((ci4*4+2)*KT + k)*CH + c4];
                    float4 w3 = *(const float4*)&ws[((ci4*4+3)*KT + k)*CH + c4];
#pragma unroll
                    for (int i = 0; i < 10; i++) {
                        float4 xv = *(const float4*)&xs[(tb[i] + k)*CH + cib];
                        acc[i].x += xv.x*w0.x + xv.y*w1.x + xv.z*w2.x + xv.w*w3.x;
                        acc[i].y += xv.x*w0.y + xv.y*w1.y + xv.z*w2.y + xv.w*w3.y;
                        acc[i].z += xv.x*w0.z + xv.y*w1.z + xv.z*w2.z + xv.w*w3.z;
                        acc[i].w += xv.x*w0.w + xv.y*w1.w + xv.z*w2.w + xv.w*w3.w;
                    }
                }
            }
        }

        // epilogue: BN fold + ReLU + residual
#pragma unroll
        for (int i = 0; i < 10; i++) {
            int tl = tg + 16*i;
            if (tl >= 150) continue;
            int t = th*150 + tl;
            long long o = (((long long)nm*TLEN + t)*VJ + v)*CH + c4;
            float4 r;
            r.x = fmaxf(acc[i].x*scl.x + sft.x, 0.f);
            r.y = fmaxf(acc[i].y*scl.y + sft.y, 0.f);
            r.z = fmaxf(acc[i].z*scl.z + sft.z, 0.f);
            r.w = fmaxf(acc[i].w*scl.w + sft.w, 0.f);
            float4 hv = *(const float4*)&h[o];
            r.x += hv.x; r.y += hv.y; r.z += hv.z; r.w += hv.w;
            *(float4*)&out[o] = r;
        }
    }
}

// ============================ launch ============================
extern "C" void kernel_launch(void* const* d_in, const int* in_sizes, int n_in,
                              void* d_out, int out_size) {
    const float* h        = (const float*)d_in[0];
    const float* adj      = (const float*)d_in[1];
    const float* gcn_w    = (const float*)d_in[2];
    const float* gcn_b    = (const float*)d_in[3];
    const float* conv_w   = (const float*)d_in[4];
    const float* conv_b   = (const float*)d_in[5];
    const float* bn_gamma = (const float*)d_in[6];
    const float* bn_beta  = (const float*)d_in[7];
    const float* bn_mean  = (const float*)d_in[8];
    const float* bn_var   = (const float*)d_in[9];
    float* out = (float*)d_out;

    const int gcn_smem  = (2*GCN_RPAD*CH + CH*CH + CH + VJ*VJ) * (int)sizeof(float);   // ~76.5 KB
    const int conv_smem = (XS_ROWS*CH + CIN_CHUNK*KT*CH) * (int)sizeof(float);          // ~97.3 KB
    cudaFuncSetAttribute(gcn_kernel,  cudaFuncAttributeMaxDynamicSharedMemorySize, gcn_smem);
    cudaFuncSetAttribute(conv_kernel, cudaFuncAttributeMaxDynamicSharedMemorySize, conv_smem);

    prep_kernel<<<1, 256>>>(adj, conv_w, conv_b, bn_gamma, bn_beta, bn_mean, bn_var);
    gcn_kernel<<<NSKEL/GCN_S, 256, gcn_smem>>>(h, gcn_w, gcn_b);
    conv_kernel<<<NMB*VJ, 256, conv_smem>>>(h, out);
}

// round 2
// speedup vs baseline: 1.0013x; 1.0013x over previous
#include <cuda_runtime.h>

// Problem constants
#define NMB 32          // N*M
#define TLEN 300
#define VJ 25
#define CH 64
#define KT 9
#define NSKEL (NMB*TLEN)          // 9600 skeletons
#define NROWS (NSKEL*VJ)          // 240000

// -------- scratch (static device allocations are allowed) --------
__device__ float g_xg[NMB*VJ*TLEN*CH];   // GCN output in (nm, v, t, c)
__device__ float g_Ahat[VJ*VJ];          // norm[v]*adj[v,u]*norm[u]
__device__ float g_wt[CH*KT*CH];         // conv weight transposed [ci][k][co]
__device__ float g_scale[CH];            // BN fold: gamma/sqrt(var+eps)
__device__ float g_shift[CH];            // (conv_b - mean)*scale + beta

// ============================ prep ============================
__global__ void prep_kernel(const float* __restrict__ adj,
                            const float* __restrict__ conv_w,
                            const float* __restrict__ conv_b,
                            const float* __restrict__ bn_gamma,
                            const float* __restrict__ bn_beta,
                            const float* __restrict__ bn_mean,
                            const float* __restrict__ bn_var) {
    __shared__ float norm[VJ];
    int tid = threadIdx.x;
    if (tid < VJ) {
        float s = 0.f;
        for (int u = 0; u < VJ; u++) s += adj[tid*VJ + u];
        norm[tid] = rsqrtf(s);
    }
    __syncthreads();
    if (tid < CH) {
        float inv = bn_gamma[tid] * rsqrtf(bn_var[tid] + 1e-5f);
        g_scale[tid] = inv;
        g_shift[tid] = (conv_b[tid] - bn_mean[tid]) * inv + bn_beta[tid];
    }
    for (int i = tid; i < VJ*VJ; i += blockDim.x)
        g_Ahat[i] = norm[i/VJ] * adj[i] * norm[i%VJ];
    // conv_w is (co, ci, k, 1) row-major -> g_wt[ci][k][co]
    for (int i = tid; i < CH*CH*KT; i += blockDim.x) {
        int ci = i / (KT*CH);
        int k  = (i / CH) % KT;
        int co = i % CH;
        g_wt[i] = conv_w[(co*CH + ci)*KT + k];
    }
}

// ============================ GCN ============================
// Block handles 4 skeletons = 100 rows (padded to 112).
// smem: hs[112][64], hw[112][64], Ws[64][64], gb[64], Ah[625]
#define GCN_S 4
#define GCN_ROWS (GCN_S*VJ)   // 100
#define GCN_RPAD 112

__global__ __launch_bounds__(256, 2)
void gcn_kernel(const float* __restrict__ h,
                const float* __restrict__ gcn_w,
                const float* __restrict__ gcn_b) {
    extern __shared__ float sm[];
    float* hs = sm;                         // 112*64
    float* hw = hs + GCN_RPAD*CH;           // 112*64
    float* Ws = hw + GCN_RPAD*CH;           // 64*64
    float* gb = Ws + CH*CH;                 // 64
    float* Ah = gb + CH;                    // 625

    const int tid = threadIdx.x;
    const int g0  = blockIdx.x * GCN_S;
    const float* hbase = h + (long long)g0 * VJ * CH;

    for (int i = tid; i < GCN_RPAD*CH; i += 256)
        hs[i] = (i < GCN_ROWS*CH) ? hbase[i] : 0.f;
    for (int i = tid; i < CH*CH; i += 256) Ws[i] = gcn_w[i];
    for (int i = tid; i < VJ*VJ; i += 256) Ah[i] = g_Ahat[i];
    if (tid < CH) gb[tid] = gcn_b[tid];
    __syncthreads();

    const int tx = tid & 15, ty = tid >> 4;
    const int c4 = tx * 4;

    // GEMM: hw = hs @ Ws, thread tile = 7 rows x 4 cols
    float4 acc[7];
#pragma unroll
    for (int j = 0; j < 7; j++) acc[j] = make_float4(0.f,0.f,0.f,0.f);

#pragma unroll 2
    for (int ci4 = 0; ci4 < 16; ci4++) {
        float4 w0 = *(const float4*)&Ws[(ci4*4+0)*CH + c4];
        float4 w1 = *(const float4*)&Ws[(ci4*4+1)*CH + c4];
        float4 w2 = *(const float4*)&Ws[(ci4*4+2)*CH + c4];
        float4 w3 = *(const float4*)&Ws[(ci4*4+3)*CH + c4];
#pragma unroll
        for (int j = 0; j < 7; j++) {
            float4 hv = *(const float4*)&hs[(ty + 16*j)*CH + ci4*4];
            acc[j].x += hv.x*w0.x + hv.y*w1.x + hv.z*w2.x + hv.w*w3.x;
            acc[j].y += hv.x*w0.y + hv.y*w1.y + hv.z*w2.y + hv.w*w3.y;
            acc[j].z += hv.x*w0.z + hv.y*w1.z + hv.z*w2.z + hv.w*w3.z;
            acc[j].w += hv.x*w0.w + hv.y*w1.w + hv.z*w2.w + hv.w*w3.w;
        }
    }
#pragma unroll
    for (int j = 0; j < 7; j++)
        *(float4*)&hw[(ty + 16*j)*CH + c4] = acc[j];
    __syncthreads();

    // Aggregation: out[s,v,c] = relu(sum_u Ah[v,u]*hw[s*25+u,c] + gb[c])
    const float4 gbv = *(const float4*)&gb[c4];
#pragma unroll
    for (int j = 0; j < 7; j++) {
        int r = ty + 16*j;
        if (r >= GCN_ROWS) break;
        int s = r / VJ, v = r % VJ;
        float4 a = gbv;
#pragma unroll
        for (int u = 0; u < VJ; u++) {
            float av = Ah[v*VJ + u];
            float4 xv = *(const float4*)&hw[(s*VJ + u)*CH + c4];
            a.x += av*xv.x; a.y += av*xv.y; a.z += av*xv.z; a.w += av*xv.w;
        }
        a.x = fmaxf(a.x, 0.f); a.y = fmaxf(a.y, 0.f);
        a.z = fmaxf(a.z, 0.f); a.w = fmaxf(a.w, 0.f);
        int g  = g0 + s;
        int nm = g / TLEN, t = g % TLEN;
        *(float4*)&g_xg[((nm*VJ + v)*TLEN + t)*CH + c4] = a;
    }
}

// ============================ Conv + BN + ReLU + residual ============================
// Block = one (nm, v) slab: x[300][64] padded to [308][64] in smem.
// Weights streamed in 8-cin chunks: ws[8][9][64].
// Thread: q = tid%16 -> 4 contiguous c_out; tg = tid/16 -> t = half*150 + tg + 16*i, i<10.
#define CIN_CHUNK 8
#define XS_ROWS (TLEN + KT - 1)  // 308

__global__ __launch_bounds__(256, 2)
void conv_kernel(const float* __restrict__ h, float* __restrict__ out) {
    extern __shared__ float sm[];
    float* xs = sm;                      // 308*64
    float* ws = xs + XS_ROWS*CH;         // 8*9*64

    const int tid = threadIdx.x;
    const int slab = blockIdx.x;         // nm*25 + v
    const int nm = slab / VJ, v = slab % VJ;
    const float* xg = g_xg + (long long)slab * TLEN * CH;

    for (int i = tid; i < XS_ROWS*CH; i += 256) {
        int row = i >> 6;  // /64
        xs[i] = (row >= 4 && row < 4 + TLEN) ? xg[i - 4*CH] : 0.f;
    }

    const int q = tid & 15, tg = tid >> 4;
    const int c4 = q * 4;
    float4 scl = make_float4(g_scale[c4], g_scale[c4+1], g_scale[c4+2], g_scale[c4+3]);
    float4 sft = make_float4(g_shift[c4], g_shift[c4+1], g_shift[c4+2], g_shift[c4+3]);

    for (int th = 0; th < 2; th++) {
        int tb[10];
#pragma unroll
        for (int i = 0; i < 10; i++) {
            int tl = tg + 16*i;
            tb[i] = (tl < 150) ? (th*150 + tl) : 0;
        }
        float4 acc[10];
#pragma unroll
        for (int i = 0; i < 10; i++) acc[i] = make_float4(0.f,0.f,0.f,0.f);

        for (int cc = 0; cc < CH/CIN_CHUNK; cc++) {
            __syncthreads();   // prior readers of ws done (also orders first xs fill)
            for (int i = tid; i < CIN_CHUNK*KT*CH; i += 256)
                ws[i] = g_wt[cc*CIN_CHUNK*KT*CH + i];
            __syncthreads();

#pragma unroll 1
            for (int k = 0; k < KT; k++) {
#pragma unroll
                for (int ci4 = 0; ci4 < 2; ci4++) {
                    int cib = cc*CIN_CHUNK + ci4*4;
                    float4 w0 = *(const float4*)&ws[((ci4*4+0)*KT + k)*CH + c4];
                    float4 w1 = *(const float4*)&ws[((ci4*4+1)*KT + k)*CH + c4];
                    float4 w2 = *(const float4*)&ws[((ci4*4+2)*KT + k)*CH + c4];
                    float4 w3 = *(const float4*)&ws[((ci4*4+3)*KT + k)*CH + c4];
#pragma unroll
                    for (int i = 0; i < 10; i++) {
                        float4 xv = *(const float4*)&xs[(tb[i] + k)*CH + cib];
                        acc[i].x += xv.x*w0.x + xv.y*w1.x + xv.z*w2.x + xv.w*w3.x;
                        acc[i].y += xv.x*w0.y + xv.y*w1.y + xv.z*w2.y + xv.w*w3.y;
                        acc[i].z += xv.x*w0.z + xv.y*w1.z + xv.z*w2.z + xv.w*w3.z;
                        acc[i].w += xv.x*w0.w + xv.y*w1.w + xv.z*w2.w + xv.w*w3.w;
                    }
                }
            }
        }

        // epilogue: BN fold + ReLU + residual
#pragma unroll
        for (int i = 0; i < 10; i++) {
            int tl = tg + 16*i;
            if (tl >= 150) continue;
            int t = th*150 + tl;
            long long o = (((long long)nm*TLEN + t)*VJ + v)*CH + c4;
            float4 r;
            r.x = fmaxf(acc[i].x*scl.x + sft.x, 0.f);
            r.y = fmaxf(acc[i].y*scl.y + sft.y, 0.f);
            r.z = fmaxf(acc[i].z*scl.z + sft.z, 0.f);
            r.w = fmaxf(acc[i].w*scl.w + sft.w, 0.f);
            float4 hv = *(const float4*)&h[o];
            r.x += hv.x; r.y += hv.y; r.z += hv.z; r.w += hv.w;
            *(float4*)&out[o] = r;
        }
    }
}

// ============================ launch ============================
extern "C" void kernel_launch(void* const* d_in, const int* in_sizes, int n_in,
                              void* d_out, int out_size) {
    const float* h        = (const float*)d_in[0];
    const float* adj      = (const float*)d_in[1];
    const float* gcn_w    = (const float*)d_in[2];
    const float* gcn_b    = (const float*)d_in[3];
    const float* conv_w   = (const float*)d_in[4];
    const float* conv_b   = (const float*)d_in[5];
    const float* bn_gamma = (const float*)d_in[6];
    const float* bn_beta  = (const float*)d_in[7];
    const float* bn_mean  = (const float*)d_in[8];
    const float* bn_var   = (const float*)d_in[9];
    float* out = (float*)d_out;

    const int gcn_smem  = (2*GCN_RPAD*CH + CH*CH + CH + VJ*VJ) * (int)sizeof(float);   // ~76.5 KB
    const int conv_smem = (XS_ROWS*CH + CIN_CHUNK*KT*CH) * (int)sizeof(float);          // ~97.3 KB
    cudaFuncSetAttribute(gcn_kernel,  cudaFuncAttributeMaxDynamicSharedMemorySize, gcn_smem);
    cudaFuncSetAttribute(conv_kernel, cudaFuncAttributeMaxDynamicSharedMemorySize, conv_smem);

    prep_kernel<<<1, 256>>>(adj, conv_w, conv_b, bn_gamma, bn_beta, bn_mean, bn_var);
    gcn_kernel<<<NSKEL/GCN_S, 256, gcn_smem>>>(h, gcn_w, gcn_b);
    conv_kernel<<<NMB*VJ, 256, conv_smem>>>(h, out);
}

// round 3
// speedup vs baseline: 2.1356x; 2.1328x over previous
#include <cuda_runtime.h>
#include <cstdint>

// Problem constants
#define NMB 32          // N*M
#define TLEN 300
#define VJ 25
#define CH 64
#define KT 9
#define NSKEL (NMB*TLEN)          // 9600 skeletons

// -------- scratch --------
__device__ float g_xg[NMB*VJ*TLEN*CH];   // GCN output in (nm, v, t, c)
__device__ float g_Ahat[VJ*VJ];          // norm[v]*adj[v,u]*norm[u]
__device__ float g_wtf[KT*CH*CH];        // conv weight [k][ci][co], tf32-rounded
__device__ float g_scale[CH];            // BN fold: gamma/sqrt(var+eps)
__device__ float g_shift[CH];            // (conv_b - mean)*scale + beta

__device__ __forceinline__ float to_tf32(float v) {
    uint32_t u;
    asm("cvt.rna.tf32.f32 %0, %1;" : "=r"(u) : "f"(v));
    return __uint_as_float(u);
}

// ============================ prep (parallel) ============================
__global__ void prep_kernel(const float* __restrict__ adj,
                            const float* __restrict__ conv_w,
                            const float* __restrict__ conv_b,
                            const float* __restrict__ bn_gamma,
                            const float* __restrict__ bn_beta,
                            const float* __restrict__ bn_mean,
                            const float* __restrict__ bn_var) {
    const int tid = threadIdx.x;
    const int gtid = blockIdx.x * blockDim.x + tid;
    const int gstride = gridDim.x * blockDim.x;

    if (blockIdx.x == 0) {
        __shared__ float norm[VJ];
        if (tid < VJ) {
            float s = 0.f;
            for (int u = 0; u < VJ; u++) s += adj[tid*VJ + u];
            norm[tid] = rsqrtf(s);
        }
        __syncthreads();
        if (tid < CH) {
            float inv = bn_gamma[tid] * rsqrtf(bn_var[tid] + 1e-5f);
            g_scale[tid] = inv;
            g_shift[tid] = (conv_b[tid] - bn_mean[tid]) * inv + bn_beta[tid];
        }
        for (int i = tid; i < VJ*VJ; i += blockDim.x)
            g_Ahat[i] = norm[i/VJ] * adj[i] * norm[i%VJ];
    }
    // conv_w is (co, ci, k, 1) -> g_wtf[k][ci][co], tf32-rounded
    for (int i = gtid; i < CH*CH*KT; i += gstride) {
        int k   = i / (CH*CH);
        int rem = i - k*(CH*CH);
        int ci  = rem >> 6;
        int co  = rem & 63;
        g_wtf[i] = to_tf32(conv_w[(co*CH + ci)*KT + k]);
    }
}

// ============================ GCN (scalar, unchanged) ============================
#define GCN_S 4
#define GCN_ROWS (GCN_S*VJ)   // 100
#define GCN_RPAD 112

__global__ __launch_bounds__(256, 2)
void gcn_kernel(const float* __restrict__ h,
                const float* __restrict__ gcn_w,
                const float* __restrict__ gcn_b) {
    extern __shared__ float sm[];
    float* hs = sm;                         // 112*64
    float* hw = hs + GCN_RPAD*CH;           // 112*64
    float* Ws = hw + GCN_RPAD*CH;           // 64*64
    float* gb = Ws + CH*CH;                 // 64
    float* Ah = gb + CH;                    // 625

    const int tid = threadIdx.x;
    const int g0  = blockIdx.x * GCN_S;
    const float* hbase = h + (long long)g0 * VJ * CH;

    for (int i = tid; i < GCN_RPAD*CH; i += 256)
        hs[i] = (i < GCN_ROWS*CH) ? hbase[i] : 0.f;
    for (int i = tid; i < CH*CH; i += 256) Ws[i] = gcn_w[i];
    for (int i = tid; i < VJ*VJ; i += 256) Ah[i] = g_Ahat[i];
    if (tid < CH) gb[tid] = gcn_b[tid];
    __syncthreads();

    const int tx = tid & 15, ty = tid >> 4;
    const int c4 = tx * 4;

    float4 acc[7];
#pragma unroll
    for (int j = 0; j < 7; j++) acc[j] = make_float4(0.f,0.f,0.f,0.f);

#pragma unroll 2
    for (int ci4 = 0; ci4 < 16; ci4++) {
        float4 w0 = *(const float4*)&Ws[(ci4*4+0)*CH + c4];
        float4 w1 = *(const float4*)&Ws[(ci4*4+1)*CH + c4];
        float4 w2 = *(const float4*)&Ws[(ci4*4+2)*CH + c4];
        float4 w3 = *(const float4*)&Ws[(ci4*4+3)*CH + c4];
#pragma unroll
        for (int j = 0; j < 7; j++) {
            float4 hv = *(const float4*)&hs[(ty + 16*j)*CH + ci4*4];
            acc[j].x += hv.x*w0.x + hv.y*w1.x + hv.z*w2.x + hv.w*w3.x;
            acc[j].y += hv.x*w0.y + hv.y*w1.y + hv.z*w2.y + hv.w*w3.y;
            acc[j].z += hv.x*w0.z + hv.y*w1.z + hv.z*w2.z + hv.w*w3.z;
            acc[j].w += hv.x*w0.w + hv.y*w1.w + hv.z*w2.w + hv.w*w3.w;
        }
    }
#pragma unroll
    for (int j = 0; j < 7; j++)
        *(float4*)&hw[(ty + 16*j)*CH + c4] = acc[j];
    __syncthreads();

    const float4 gbv = *(const float4*)&gb[c4];
#pragma unroll
    for (int j = 0; j < 7; j++) {
        int r = ty + 16*j;
        if (r >= GCN_ROWS) break;
        int s = r / VJ, v = r % VJ;
        float4 a = gbv;
#pragma unroll
        for (int u = 0; u < VJ; u++) {
            float av = Ah[v*VJ + u];
            float4 xv = *(const float4*)&hw[(s*VJ + u)*CH + c4];
            a.x += av*xv.x; a.y += av*xv.y; a.z += av*xv.z; a.w += av*xv.w;
        }
        a.x = fmaxf(a.x, 0.f); a.y = fmaxf(a.y, 0.f);
        a.z = fmaxf(a.z, 0.f); a.w = fmaxf(a.w, 0.f);
        int g  = g0 + s;
        int nm = g / TLEN, t = g % TLEN;
        *(float4*)&g_xg[((nm*VJ + v)*TLEN + t)*CH + c4] = a;
    }
}

// ============================ Conv via mma.sync tf32 ============================
// Block = half a (nm,v) slab: 150 output t-rows. 320 threads = 10 warps,
// warp w owns output rows [w*16, w*16+16) x all 64 c_out (8 n8 blocks).
// X tile in smem stride 68 (conflict-free A frags), W per-tap double-buffered
// stride 72 (conflict-free B frags). fp32 accumulate, fused BN/ReLU/residual.
#define XSTR 68
#define WSTR 72
#define XROWS 168            // 158 valid + pad for tile-9 A loads
#define CONV_THREADS 320

__global__ __launch_bounds__(CONV_THREADS, 2)
void conv_mma_kernel(const float* __restrict__ h, float* __restrict__ out) {
    extern __shared__ float sm[];
    float* xs = sm;                      // XROWS*XSTR
    float* wb = sm + XROWS*XSTR;         // 2 * 64*WSTR

    const int tid  = threadIdx.x;
    const int bid  = blockIdx.x;
    const int slab = bid >> 1;           // nm*25 + v
    const int half = bid & 1;
    const int nm = slab / VJ, v = slab % VJ;
    const int tbase = half * 150;
    const float* xg = g_xg + (long long)slab * TLEN * CH;

    // Fill X (tf32-rounded): smem row r <-> global t = tbase - 4 + r
    for (int i = tid; i < XROWS*CH; i += CONV_THREADS) {
        int r = i >> 6, c = i & 63;
        int tg = tbase - 4 + r;
        float val = 0.f;
        if (tg >= 0 && tg < TLEN && r < 158) val = xg[tg*CH + c];
        xs[r*XSTR + c] = to_tf32(val);
    }

    // Prefetch W tap 0 (already tf32 in g_wtf)
    float wtmp[13];
#pragma unroll
    for (int j = 0; j < 13; j++) {
        int i = tid + j*CONV_THREADS;
        wtmp[j] = (i < CH*CH) ? g_wtf[i] : 0.f;
    }
#pragma unroll
    for (int j = 0; j < 13; j++) {
        int i = tid + j*CONV_THREADS;
        if (i < CH*CH) wb[(i >> 6)*WSTR + (i & 63)] = wtmp[j];
    }
    __syncthreads();

    const int lane = tid & 31, w = tid >> 5;
    const int gID = lane >> 2, tig = lane & 3;
    const int arow = w*16 + gID;

    float acc[8][4];
#pragma unroll
    for (int nb = 0; nb < 8; nb++)
#pragma unroll
        for (int j = 0; j < 4; j++) acc[nb][j] = 0.f;

    for (int k = 0; k < KT; k++) {
        const float* wcur = wb + (k & 1) * CH*WSTR;

        // prefetch next tap into registers (LDG in flight during compute)
        if (k < KT-1) {
            const float* wsrc = g_wtf + (k+1)*CH*CH;
#pragma unroll
            for (int j = 0; j < 13; j++) {
                int i = tid + j*CONV_THREADS;
                wtmp[j] = (i < CH*CH) ? wsrc[i] : 0.f;
            }
        }

        // GEMM: out[t][co] += X[t+k][ci] * Wk[ci][co], K=64 as 8 k-slices
#pragma unroll
        for (int kk = 0; kk < 8; kk++) {
            const float* xp = xs + (arow + k)*XSTR + kk*8 + tig;
            uint32_t a0 = __float_as_uint(xp[0]);
            uint32_t a1 = __float_as_uint(xp[8*XSTR]);
            uint32_t a2 = __float_as_uint(xp[4]);
            uint32_t a3 = __float_as_uint(xp[8*XSTR + 4]);
            const float* wp = wcur + (kk*8 + tig)*WSTR + gID;
#pragma unroll
            for (int nb = 0; nb < 8; nb++) {
                uint32_t b0 = __float_as_uint(wp[nb*8]);
                uint32_t b1 = __float_as_uint(wp[nb*8 + 4*WSTR]);
                asm volatile(
                    "mma.sync.aligned.m16n8k8.row.col.f32.tf32.tf32.f32 "
                    "{%0,%1,%2,%3}, {%4,%5,%6,%7}, {%8,%9}, {%0,%1,%2,%3};"
                    : "+f"(acc[nb][0]), "+f"(acc[nb][1]),
                      "+f"(acc[nb][2]), "+f"(acc[nb][3])
                    : "r"(a0), "r"(a1), "r"(a2), "r"(a3), "r"(b0), "r"(b1));
            }
        }

        // store next tap to the other buffer
        if (k < KT-1) {
            float* wnext = wb + ((k+1) & 1) * CH*WSTR;
#pragma unroll
            for (int j = 0; j < 13; j++) {
                int i = tid + j*CONV_THREADS;
                if (i < CH*CH) wnext[(i >> 6)*WSTR + (i & 63)] = wtmp[j];
            }
        }
        __syncthreads();
    }

    // Epilogue: BN fold + ReLU + residual. D frag: rows {arow, arow+8}, cols 2*tig+{0,1}
#pragma unroll
    for (int nb = 0; nb < 8; nb++) {
        int co = nb*8 + tig*2;
        float2 scl = *(const float2*)&g_scale[co];
        float2 sft = *(const float2*)&g_shift[co];
#pragma unroll
        for (int rr = 0; rr < 2; rr++) {
            int tl = w*16 + gID + rr*8;
            if (tl >= 150) continue;
            int t = tbase + tl;
            long long o = (((long long)nm*TLEN + t)*VJ + v)*CH + co;
            float x0 = fmaxf(acc[nb][rr*2+0]*scl.x + sft.x, 0.f);
            float x1 = fmaxf(acc[nb][rr*2+1]*scl.y + sft.y, 0.f);
            float2 hv = *(const float2*)&h[o];
            float2 r2 = make_float2(x0 + hv.x, x1 + hv.y);
            *(float2*)&out[o] = r2;
        }
    }
}

// ============================ launch ============================
extern "C" void kernel_launch(void* const* d_in, const int* in_sizes, int n_in,
                              void* d_out, int out_size) {
    const float* h        = (const float*)d_in[0];
    const float* adj      = (const float*)d_in[1];
    const float* gcn_w    = (const float*)d_in[2];
    const float* gcn_b    = (const float*)d_in[3];
    const float* conv_w   = (const float*)d_in[4];
    const float* conv_b   = (const float*)d_in[5];
    const float* bn_gamma = (const float*)d_in[6];
    const float* bn_beta  = (const float*)d_in[7];
    const float* bn_mean  = (const float*)d_in[8];
    const float* bn_var   = (const float*)d_in[9];
    float* out = (float*)d_out;

    const int gcn_smem  = (2*GCN_RPAD*CH + CH*CH + CH + VJ*VJ) * (int)sizeof(float);
    const int conv_smem = (XROWS*XSTR + 2*CH*WSTR) * (int)sizeof(float);   // 82,560 B
    cudaFuncSetAttribute(gcn_kernel,  cudaFuncAttributeMaxDynamicSharedMemorySize, gcn_smem);
    cudaFuncSetAttribute(conv_mma_kernel, cudaFuncAttributeMaxDynamicSharedMemorySize, conv_smem);

    prep_kernel<<<64, 256>>>(adj, conv_w, conv_b, bn_gamma, bn_beta, bn_mean, bn_var);
    gcn_kernel<<<NSKEL/GCN_S, 256, gcn_smem>>>(h, gcn_w, gcn_b);
    conv_mma_kernel<<<NMB*VJ*2, CONV_THREADS, conv_smem>>>(h, out);
}